// round 11
// baseline (speedup 1.0000x reference)
#include <cuda_runtime.h>
#include <cuda_fp16.h>
#include <cstdint>

#define N_NODES 100000
#define N_EDGES 1600000
#define NF 128
#define NC 10
#define NG 64
#define RW 8   // half2 lanes per row: 5 class lanes + aux lane + 2 pad = 32B sector

#define E2_BLOCKS ((N_EDGES / 2 + 255) / 256)           // 3125 (2 edges/thread)
#define U_BLOCKS  ((N_NODES + 255) / 256)               // 391
#define HF_UINTS  (2 * N_NODES * RW)                    // 1.6M
#define ZB_BLOCKS ((HF_UINTS / 8 + 255) / 256)          // 782 (8 uints = 32B/thread)

// ---------------- scratch ----------------
__device__ __align__(32) float    d_deg[N_NODES];
__device__ __align__(16) int2     d_rc[N_EDGES];
__device__ __align__(32) unsigned d_uf[N_NODES * RW];    // dis*u fp16x2; lane5=(dis,0)
__device__ __align__(32) unsigned d_hf[HF_UINTS];        // [h1f | h2f]
__device__ __align__(16) float    d_a1[N_NODES];
__device__ __align__(16) float    d_bw[12];              // b1 @ W2
__device__ float d_pool[NG * NC];
__device__ float d_gcnt[NG];
__device__ int   d_is64;

#define H1F d_hf
#define H2F (d_hf + N_NODES * RW)

// ---------------- helpers ----------------
__device__ __forceinline__ void redv4h(unsigned* addr, uint4 v) {
    asm volatile("red.global.add.noftz.v4.f16x2 [%0], {%1,%2,%3,%4};"
                 :: "l"(addr), "r"(v.x), "r"(v.y), "r"(v.z), "r"(v.w) : "memory");
}
__device__ __forceinline__ void redv2h(unsigned* addr, unsigned a, unsigned b) {
    asm volatile("red.global.add.noftz.v2.f16x2 [%0], {%1,%2};"
                 :: "l"(addr), "r"(a), "r"(b) : "memory");
}
__device__ __forceinline__ void redh(unsigned* addr, unsigned a) {
    asm volatile("red.global.add.noftz.f16x2 [%0], %1;"
                 :: "l"(addr), "r"(a) : "memory");
}
__device__ __forceinline__ unsigned pack2(float lo, float hi) {
    __half2 h = __floats2half2_rn(lo, hi);
    return *reinterpret_cast<unsigned*>(&h);
}
__device__ __forceinline__ float2 unpack2(unsigned u) {
    __half2 h = *reinterpret_cast<__half2*>(&u);
    return make_float2(__low2float(h), __high2float(h));
}

// detect int64 indices + bw = b1 @ W2
__global__ void __launch_bounds__(128) k_init(const void* ei,
                                              const float* __restrict__ W2,
                                              const float* __restrict__ b1) {
    if (blockIdx.x == 0) {
        if (threadIdx.x < 32) {
            const int* p = (const int*)ei;
            unsigned ok = __ballot_sync(0xFFFFFFFFu, p[2 * threadIdx.x + 1] == 0);
            if (threadIdx.x == 0) d_is64 = (ok == 0xFFFFFFFFu) ? 1 : 0;
        }
        return;
    }
    int t = threadIdx.x;
    if (t < NC) {
        float a = 0.0f;
        for (int f = 0; f < NF; f++) a += b1[f] * W2[f * NC + t];
        d_bw[t] = a;
    }
    if (t == 0) { d_bw[10] = 0.0f; d_bw[11] = 0.0f; }
}

// blocks [0,E2): deg[col]+=1 (2 edges/thread); blocks [E2, E2+ZB): zero d_hf
__global__ void __launch_bounds__(256) k_deg(const void* ei) {
    if (blockIdx.x < E2_BLOCKS) {
        int t = blockIdx.x * 256 + threadIdx.x;
        if (t * 2 >= N_EDGES) return;
        int c0, c1;
        if (d_is64) {
            longlong2 v = __ldg((const longlong2*)ei + (N_EDGES / 2) + t);
            c0 = (int)v.x; c1 = (int)v.y;
        } else {
            int2 v = __ldg((const int2*)ei + (N_EDGES / 2) + t);
            c0 = v.x; c1 = v.y;
        }
        atomicAdd(&d_deg[c0], 1.0f);
        atomicAdd(&d_deg[c1], 1.0f);
    } else {
        int t = (blockIdx.x - E2_BLOCKS) * 256 + threadIdx.x;
        uint4* p = (uint4*)d_hf + t * 2;
        if (t * 8 < HF_UINTS) {
            p[0] = make_uint4(0u, 0u, 0u, 0u);
            p[1] = make_uint4(0u, 0u, 0u, 0u);
        }
    }
}

// blocks [0,E2): pack rc (2 edges/thread);
// blocks [E2, E2+U): uf = fp16(dis * (x @ (W1@W2))), lane5 = dis
__global__ void __launch_bounds__(256) k_fat(const void* ei, const float* __restrict__ x,
                                             const float* __restrict__ W1,
                                             const float* __restrict__ W2) {
    if (blockIdx.x < E2_BLOCKS) {
        int t = blockIdx.x * 256 + threadIdx.x;
        if (t * 2 >= N_EDGES) return;
        int r0, r1, c0, c1;
        if (d_is64) {
            longlong2 vr = __ldg((const longlong2*)ei + t);
            longlong2 vc = __ldg((const longlong2*)ei + (N_EDGES / 2) + t);
            r0 = (int)vr.x; r1 = (int)vr.y; c0 = (int)vc.x; c1 = (int)vc.y;
        } else {
            int2 vr = __ldg((const int2*)ei + t);
            int2 vc = __ldg((const int2*)ei + (N_EDGES / 2) + t);
            r0 = vr.x; r1 = vr.y; c0 = vc.x; c1 = vc.y;
        }
        ((int4*)d_rc)[t] = make_int4(r0, c0, r1, c1);
    } else {
        // per-block Wc = W1 @ W2 into shared, then u rows
        __shared__ float4 sWc[NF * 3];                // [k][lane] padded 12-wide
        int t = threadIdx.x;
        {
            __shared__ float sW2[NF * NC];
            for (int j = t; j < NF * NC; j += 256) sW2[j] = __ldg(&W2[j]);
            __syncthreads();
            for (int k = t; k < NF; k += 256) {
                float acc[NC];
#pragma unroll
                for (int c = 0; c < NC; c++) acc[c] = 0.0f;
                for (int f = 0; f < NF; f++) {
                    float w = __ldg(&W1[k * NF + f]);
#pragma unroll
                    for (int c = 0; c < NC; c++) acc[c] += w * sW2[f * NC + c];
                }
                sWc[k * 3 + 0] = make_float4(acc[0], acc[1], acc[2], acc[3]);
                sWc[k * 3 + 1] = make_float4(acc[4], acc[5], acc[6], acc[7]);
                sWc[k * 3 + 2] = make_float4(acc[8], acc[9], 0.0f, 0.0f);
            }
            __syncthreads();
        }
        int n = (blockIdx.x - E2_BLOCKS) * 256 + t;
        if (n >= N_NODES) return;
        float4 a0 = make_float4(0,0,0,0), a1 = a0, a2 = a0;
        const float4* xr = (const float4*)(x + (size_t)n * NF);
#pragma unroll 4
        for (int k4 = 0; k4 < NF / 4; k4++) {
            float4 xv = __ldg(&xr[k4]);
#pragma unroll
            for (int kk = 0; kk < 4; kk++) {
                float s = (kk == 0) ? xv.x : (kk == 1) ? xv.y : (kk == 2) ? xv.z : xv.w;
                int k = k4 * 4 + kk;
                float4 w0 = sWc[k * 3 + 0], w1 = sWc[k * 3 + 1], w2 = sWc[k * 3 + 2];
                a0.x += s * w0.x; a0.y += s * w0.y; a0.z += s * w0.z; a0.w += s * w0.w;
                a1.x += s * w1.x; a1.y += s * w1.y; a1.z += s * w1.z; a1.w += s * w1.w;
                a2.x += s * w2.x; a2.y += s * w2.y;
            }
        }
        float dis = rsqrtf(d_deg[n] + 1.0f);
        uint4* o = (uint4*)(d_uf + (size_t)n * RW);
        o[0] = make_uint4(pack2(a0.x * dis, a0.y * dis),
                          pack2(a0.z * dis, a0.w * dis),
                          pack2(a1.x * dis, a1.y * dis),
                          pack2(a1.z * dis, a1.w * dis));
        o[1] = make_uint4(pack2(a2.x * dis, a2.y * dis),
                          pack2(dis, 0.0f), 0u, 0u);
    }
}

// pass1: scatter u' rows into h1f, 2 edges/thread (v4 + v2 REDs)
__global__ void __launch_bounds__(256) k_pass1() {
    int t = blockIdx.x * 256 + threadIdx.x;
    if (t * 2 >= N_EDGES) return;
    int4 rr = __ldg((const int4*)d_rc + t);   // edgeA: rr.x->rr.y, edgeB: rr.z->rr.w
    const uint4* sA = (const uint4*)(d_uf + (size_t)rr.x * RW);
    const uint4* sB = (const uint4*)(d_uf + (size_t)rr.z * RW);
    uint4 pa = __ldg(&sA[0]); uint2 qa = __ldg((const uint2*)(sA + 1));
    uint4 pb = __ldg(&sB[0]); uint2 qb = __ldg((const uint2*)(sB + 1));
    unsigned* dA = H1F + (size_t)rr.y * RW;
    unsigned* dB = H1F + (size_t)rr.w * RW;
    redv4h(dA, pa); redv2h(dA + 4, qa.x, qa.y);
    redv4h(dB, pb); redv2h(dB + 4, qb.x, qb.y);
}

// post1: h1_full = dis*(S + u') + a1*bw ; write h1' = dis*h1_full, lane5=0
__global__ void __launch_bounds__(256) k_post1() {
    __shared__ float sbw[NC];
    if (threadIdx.x < NC) sbw[threadIdx.x] = d_bw[threadIdx.x];
    __syncthreads();
    int n = blockIdx.x * blockDim.x + threadIdx.x;
    if (n >= N_NODES) return;
    float dis = rsqrtf(d_deg[n] + 1.0f);
    uint4* hr = (uint4*)(H1F + (size_t)n * RW);
    const uint4* ur = (const uint4*)(d_uf + (size_t)n * RW);
    uint4 h0 = hr[0], h1 = hr[1];
    uint4 u0 = ur[0], u1 = ur[1];
    float S[NC], U[NC];
    {
        float2 a, b;
        a = unpack2(h0.x); S[0]=a.x; S[1]=a.y;  a = unpack2(h0.y); S[2]=a.x; S[3]=a.y;
        a = unpack2(h0.z); S[4]=a.x; S[5]=a.y;  a = unpack2(h0.w); S[6]=a.x; S[7]=a.y;
        a = unpack2(h1.x); S[8]=a.x; S[9]=a.y;
        b = unpack2(u0.x); U[0]=b.x; U[1]=b.y;  b = unpack2(u0.y); U[2]=b.x; U[3]=b.y;
        b = unpack2(u0.z); U[4]=b.x; U[5]=b.y;  b = unpack2(u0.w); U[6]=b.x; U[7]=b.y;
        b = unpack2(u1.x); U[8]=b.x; U[9]=b.y;
    }
    float sumdis = unpack2(h1.y).x;
    float a1 = dis * (sumdis + dis);
    d_a1[n] = a1;
#pragma unroll
    for (int c = 0; c < NC; c++) {
        float h = dis * (S[c] + U[c]) + a1 * sbw[c];
        S[c] = dis * h;
    }
    hr[0] = make_uint4(pack2(S[0],S[1]), pack2(S[2],S[3]), pack2(S[4],S[5]), pack2(S[6],S[7]));
    hr[1] = make_uint4(pack2(S[8],S[9]), 0u, 0u, 0u);
}

// pass2: scatter h1' rows into h2f, 2 edges/thread (v4 + scalar REDs)
__global__ void __launch_bounds__(256) k_pass2() {
    int t = blockIdx.x * 256 + threadIdx.x;
    if (t * 2 >= N_EDGES) return;
    int4 rr = __ldg((const int4*)d_rc + t);
    const uint4* sA = (const uint4*)(H1F + (size_t)rr.x * RW);
    const uint4* sB = (const uint4*)(H1F + (size_t)rr.z * RW);
    uint4 pa = __ldg(&sA[0]); unsigned qa = __ldg((const unsigned*)(sA + 1));
    uint4 pb = __ldg(&sB[0]); unsigned qb = __ldg((const unsigned*)(sB + 1));
    unsigned* dA = H2F + (size_t)rr.y * RW;
    unsigned* dB = H2F + (size_t)rr.w * RW;
    redv4h(dA, pa); redh(dA + 4, qa);
    redv4h(dB, pb); redh(dB + 4, qb);
}

// pool: val = dis*(T + h1') + a1*b2 ; per-graph mean-pool accumulate
__global__ void __launch_bounds__(256) k_pool(const void* batch, const float* __restrict__ b2) {
    __shared__ float sp[NG * NC];
    __shared__ float sc[NG];
    __shared__ float sb2[NC];
    int t = threadIdx.x;
    for (int j = t; j < NG * NC; j += 256) sp[j] = 0.0f;
    if (t < NG) sc[t] = 0.0f;
    if (t < NC) sb2[t] = b2[t];
    __syncthreads();
    int n = blockIdx.x * 256 + t;
    if (n < N_NODES) {
        int g = d_is64 ? (int)((const long long*)batch)[n] : ((const int*)batch)[n];
        float dis = rsqrtf(d_deg[n] + 1.0f);
        float a1 = d_a1[n];
        const unsigned* tr = H2F + (size_t)n * RW;
        const unsigned* qr = H1F + (size_t)n * RW;
#pragma unroll
        for (int q = 0; q < 5; q++) {
            float2 tv = unpack2(tr[q]);
            float2 qv = unpack2(qr[q]);
            atomicAdd(&sp[g * NC + 2*q],     dis * (tv.x + qv.x) + a1 * sb2[2*q]);
            atomicAdd(&sp[g * NC + 2*q + 1], dis * (tv.y + qv.y) + a1 * sb2[2*q+1]);
        }
        atomicAdd(&sc[g], 1.0f);
    }
    __syncthreads();
    for (int j = t; j < NG * NC; j += 256)
        if (sp[j] != 0.0f) atomicAdd(&d_pool[j], sp[j]);
    if (t < NG && sc[t] != 0.0f) atomicAdd(&d_gcnt[t], sc[t]);
}

// divide by counts, log_softmax
__global__ void __launch_bounds__(64) k_final(float* __restrict__ out) {
    int g = threadIdx.x;
    float inv = 1.0f / fmaxf(d_gcnt[g], 1.0f);
    float p[NC];
#pragma unroll
    for (int c = 0; c < NC; c++) p[c] = d_pool[g * NC + c] * inv;
    float mx = p[0];
#pragma unroll
    for (int c = 1; c < NC; c++) mx = fmaxf(mx, p[c]);
    float se = 0.0f;
#pragma unroll
    for (int c = 0; c < NC; c++) se += expf(p[c] - mx);
    float l = logf(se);
#pragma unroll
    for (int c = 0; c < NC; c++) out[g * NC + c] = p[c] - mx - l;
}

// ---------------- launch ----------------
extern "C" void kernel_launch(void* const* d_in, const int* in_sizes, int n_in,
                              void* d_out, int out_size) {
    const float* x = (const float*)d_in[0];
    const void*  ei = d_in[1];
    const void*  batch = d_in[2];
    int w = (in_sizes[3] == 1) ? 4 : 3;
    const float* W1 = (const float*)d_in[w + 0];
    const float* b1 = (const float*)d_in[w + 1];
    const float* W2 = (const float*)d_in[w + 2];
    const float* b2 = (const float*)d_in[w + 3];
    float* out = (float*)d_out;

    void* p;
    cudaGetSymbolAddress(&p, d_deg);  cudaMemsetAsync(p, 0, sizeof(float) * N_NODES);
    cudaGetSymbolAddress(&p, d_pool); cudaMemsetAsync(p, 0, sizeof(float) * NG * NC);
    cudaGetSymbolAddress(&p, d_gcnt); cudaMemsetAsync(p, 0, sizeof(float) * NG);

    k_init<<<2, 128>>>(ei, W2, b1);
    k_deg <<<E2_BLOCKS + ZB_BLOCKS, 256>>>(ei);
    k_fat <<<E2_BLOCKS + U_BLOCKS, 256>>>(ei, x, W1, W2);

    k_pass1<<<E2_BLOCKS, 256>>>();
    k_post1<<<U_BLOCKS, 256>>>();
    k_pass2<<<E2_BLOCKS, 256>>>();

    k_pool<<<U_BLOCKS, 256>>>(batch, b2);
    k_final<<<1, NG>>>(out);
}

// round 12
// speedup vs baseline: 1.2740x; 1.2740x over previous
#include <cuda_runtime.h>
#include <cuda_fp16.h>
#include <cstdint>

#define N_NODES 100000
#define N_EDGES 1600000
#define NF 128
#define NC 10
#define NG 64
#define RW 8   // half2 lanes per row: 5 class lanes + aux lane + 2 pad = 32B sector

#define PACK_BLOCKS ((N_EDGES + 255) / 256)   // 6250
#define U_BLOCKS    ((N_NODES + 255) / 256)   // 391
#define HF_UINTS    (2 * N_NODES * RW)        // 1.6M
#define ZB_BLOCKS   ((HF_UINTS / 8 + 255) / 256)  // 782 (8 uints = 32B/thread)

// ---------------- scratch ----------------
__device__ __align__(32) float    d_deg[N_NODES];        // edge-only degree
__device__ __align__(16) int2     d_rc[N_EDGES];
__device__ __align__(16) float    d_u [N_NODES * 12];    // x @ Wc (f32, 12-wide)
__device__ __align__(32) unsigned d_uf[N_NODES * RW];    // dis*u fp16x2; lane5=(dis,0)
__device__ __align__(32) unsigned d_hf[HF_UINTS];        // [h1f | h2f]
__device__ __align__(16) float    d_a1[N_NODES];
__device__ __align__(16) float    d_Wc[NF * 12];
__device__ __align__(16) float    d_bw[12];
__device__ float d_pool[NG * NC];
__device__ float d_gcnt[NG];
__device__ int   d_is64;

#define H1F d_hf
#define H2F (d_hf + N_NODES * RW)

// ---------------- helpers ----------------
__device__ __forceinline__ int read_idx(const void* p, long long i, int is64) {
    return is64 ? (int)((const long long*)p)[i] : ((const int*)p)[i];
}
__device__ __forceinline__ void redv4h(unsigned* addr, uint4 v) {
    asm volatile("red.global.add.noftz.v4.f16x2 [%0], {%1,%2,%3,%4};"
                 :: "l"(addr), "r"(v.x), "r"(v.y), "r"(v.z), "r"(v.w) : "memory");
}
__device__ __forceinline__ void redv2h(unsigned* addr, unsigned a, unsigned b) {
    asm volatile("red.global.add.noftz.v2.f16x2 [%0], {%1,%2};"
                 :: "l"(addr), "r"(a), "r"(b) : "memory");
}
__device__ __forceinline__ void redh(unsigned* addr, unsigned a) {
    asm volatile("red.global.add.noftz.f16x2 [%0], %1;"
                 :: "l"(addr), "r"(a) : "memory");
}
__device__ __forceinline__ unsigned pack2(float lo, float hi) {
    __half2 h = __floats2half2_rn(lo, hi);
    return *reinterpret_cast<unsigned*>(&h);
}
__device__ __forceinline__ float2 unpack2(unsigned u) {
    __half2 h = *reinterpret_cast<__half2*>(&u);
    return make_float2(__low2float(h), __high2float(h));
}

// detect int64 indices (block 0) + Wc = W1@W2, bw = b1@W2 (block 1)
__global__ void __launch_bounds__(128) k_init(const void* ei,
                                              const float* __restrict__ W1,
                                              const float* __restrict__ W2,
                                              const float* __restrict__ b1) {
    if (blockIdx.x == 0) {
        if (threadIdx.x < 32) {
            const int* p = (const int*)ei;
            unsigned ok = __ballot_sync(0xFFFFFFFFu, p[2 * threadIdx.x + 1] == 0);
            if (threadIdx.x == 0) d_is64 = (ok == 0xFFFFFFFFu) ? 1 : 0;
        }
        return;
    }
    __shared__ float sW2[NF * NC];
    int t = threadIdx.x;                       // t = input-feature row
    for (int j = t; j < NF * NC; j += NF) sW2[j] = W2[j];
    __syncthreads();
    float acc[NC];
#pragma unroll
    for (int c = 0; c < NC; c++) acc[c] = 0.0f;
    for (int f = 0; f < NF; f++) {
        float w = W1[t * NF + f];
#pragma unroll
        for (int c = 0; c < NC; c++) acc[c] += w * sW2[f * NC + c];
    }
#pragma unroll
    for (int c = 0; c < NC; c++) d_Wc[t * 12 + c] = acc[c];
    d_Wc[t * 12 + 10] = 0.0f; d_Wc[t * 12 + 11] = 0.0f;
    if (t < NC) {
        float a = 0.0f;
        for (int f = 0; f < NF; f++) a += b1[f] * sW2[f * NC + t];
        d_bw[t] = a;
    }
    if (t == 0) { d_bw[10] = 0.0f; d_bw[11] = 0.0f; }
}

// Fat: blocks [0,PACK): pack rc + degree atomics;
//      blocks [PACK, PACK+U): u = x @ Wc (f32);
//      blocks [PACK+U, PACK+U+ZB): zero d_hf (independent of the rest)
__global__ void __launch_bounds__(256) k_fat(const void* ei, const float* __restrict__ x) {
    if (blockIdx.x < PACK_BLOCKS) {
        int e = blockIdx.x * 256 + threadIdx.x;
        if (e >= N_EDGES) return;
        int is64 = d_is64;
        int r = read_idx(ei, e, is64);
        int c = read_idx(ei, (long long)N_EDGES + e, is64);
        d_rc[e] = make_int2(r, c);
        atomicAdd(&d_deg[c], 1.0f);
    } else if (blockIdx.x < PACK_BLOCKS + U_BLOCKS) {
        __shared__ float4 sWc[NF * 3];
        int t = threadIdx.x;
        for (int j = t; j < NF * 3; j += 256) sWc[j] = ((const float4*)d_Wc)[j];
        __syncthreads();
        int n = (blockIdx.x - PACK_BLOCKS) * 256 + t;
        if (n >= N_NODES) return;
        float4 a0 = make_float4(0,0,0,0), a1 = a0, a2 = a0;
        const float4* xr = (const float4*)(x + (size_t)n * NF);
#pragma unroll 4
        for (int k4 = 0; k4 < NF / 4; k4++) {
            float4 xv = __ldg(&xr[k4]);
#pragma unroll
            for (int kk = 0; kk < 4; kk++) {
                float s = (kk == 0) ? xv.x : (kk == 1) ? xv.y : (kk == 2) ? xv.z : xv.w;
                int k = k4 * 4 + kk;
                float4 w0 = sWc[k * 3 + 0], w1 = sWc[k * 3 + 1], w2 = sWc[k * 3 + 2];
                a0.x += s * w0.x; a0.y += s * w0.y; a0.z += s * w0.z; a0.w += s * w0.w;
                a1.x += s * w1.x; a1.y += s * w1.y; a1.z += s * w1.z; a1.w += s * w1.w;
                a2.x += s * w2.x; a2.y += s * w2.y; a2.z += s * w2.z; a2.w += s * w2.w;
            }
        }
        float4* ur = (float4*)(d_u + (size_t)n * 12);
        ur[0] = a0; ur[1] = a1; ur[2] = a2;
    } else {
        int t = (blockIdx.x - PACK_BLOCKS - U_BLOCKS) * 256 + threadIdx.x;
        if (t * 8 < HF_UINTS) {
            uint4* p = (uint4*)d_hf + t * 2;
            p[0] = make_uint4(0u, 0u, 0u, 0u);
            p[1] = make_uint4(0u, 0u, 0u, 0u);
        }
    }
}

// u'f16 = dis * u ; lane5 = (dis, 0); lanes 6,7 = 0
__global__ void __launch_bounds__(256) k_scale() {
    int n = blockIdx.x * blockDim.x + threadIdx.x;
    if (n >= N_NODES) return;
    float dis = rsqrtf(d_deg[n] + 1.0f);
    const float4* ur = (const float4*)(d_u + (size_t)n * 12);
    float4 u0 = ur[0], u1 = ur[1], u2 = ur[2];
    uint4* o = (uint4*)(d_uf + (size_t)n * RW);
    o[0] = make_uint4(pack2(u0.x * dis, u0.y * dis),
                      pack2(u0.z * dis, u0.w * dis),
                      pack2(u1.x * dis, u1.y * dis),
                      pack2(u1.z * dis, u1.w * dis));
    o[1] = make_uint4(pack2(u2.x * dis, u2.y * dis),
                      pack2(dis, 0.0f), 0u, 0u);
}

// pass1: scatter-copy u' rows into h1f: one v4 RED + one v2 RED (lanes 0-5)
__global__ void __launch_bounds__(256) k_pass1() {
    int e = blockIdx.x * blockDim.x + threadIdx.x;
    if (e >= N_EDGES) return;
    int2 rc = __ldg(&d_rc[e]);
    const uint4* s = (const uint4*)(d_uf + (size_t)rc.x * RW);
    uint4 p0 = __ldg(&s[0]);
    uint2 p1 = __ldg((const uint2*)(s + 1));  // .x=lane4, .y=lane5(dis)
    unsigned* d = H1F + (size_t)rc.y * RW;
    redv4h(d, p0);
    redv2h(d + 4, p1.x, p1.y);
}

// post1: h1_full = dis*(S + u') + a1*bw ; write h1' = dis*h1_full (fp16), lane5=0
__global__ void __launch_bounds__(256) k_post1() {
    __shared__ float sbw[NC];
    if (threadIdx.x < NC) sbw[threadIdx.x] = d_bw[threadIdx.x];
    __syncthreads();
    int n = blockIdx.x * blockDim.x + threadIdx.x;
    if (n >= N_NODES) return;
    float dis = rsqrtf(d_deg[n] + 1.0f);
    uint4* hr = (uint4*)(H1F + (size_t)n * RW);
    const uint4* ur = (const uint4*)(d_uf + (size_t)n * RW);
    uint4 h0 = hr[0], h1 = hr[1];
    uint4 u0 = ur[0], u1 = ur[1];
    float S[NC], U[NC];
    {
        float2 a, b;
        a = unpack2(h0.x); S[0]=a.x; S[1]=a.y;  a = unpack2(h0.y); S[2]=a.x; S[3]=a.y;
        a = unpack2(h0.z); S[4]=a.x; S[5]=a.y;  a = unpack2(h0.w); S[6]=a.x; S[7]=a.y;
        a = unpack2(h1.x); S[8]=a.x; S[9]=a.y;
        b = unpack2(u0.x); U[0]=b.x; U[1]=b.y;  b = unpack2(u0.y); U[2]=b.x; U[3]=b.y;
        b = unpack2(u0.z); U[4]=b.x; U[5]=b.y;  b = unpack2(u0.w); U[6]=b.x; U[7]=b.y;
        b = unpack2(u1.x); U[8]=b.x; U[9]=b.y;
    }
    float sumdis = unpack2(h1.y).x;
    float a1 = dis * (sumdis + dis);
    d_a1[n] = a1;
#pragma unroll
    for (int c = 0; c < NC; c++) {
        float h = dis * (S[c] + U[c]) + a1 * sbw[c];
        S[c] = dis * h;                       // prescale for pass2
    }
    hr[0] = make_uint4(pack2(S[0],S[1]), pack2(S[2],S[3]), pack2(S[4],S[5]), pack2(S[6],S[7]));
    hr[1] = make_uint4(pack2(S[8],S[9]), 0u, 0u, 0u);
}

// pass2: scatter-copy h1' rows into h2f: one v4 RED + one scalar RED (lanes 0-4)
__global__ void __launch_bounds__(256) k_pass2() {
    int e = blockIdx.x * blockDim.x + threadIdx.x;
    if (e >= N_EDGES) return;
    int2 rc = __ldg(&d_rc[e]);
    const uint4* s = (const uint4*)(H1F + (size_t)rc.x * RW);
    uint4 p0 = __ldg(&s[0]);
    unsigned p4 = __ldg((const unsigned*)(s + 1));   // lane4
    unsigned* d = H2F + (size_t)rc.y * RW;
    redv4h(d, p0);
    redh(d + 4, p4);
}

// pool: val = dis*(T + h1') + a1*b2 ; per-graph mean-pool accumulate
__global__ void __launch_bounds__(256) k_pool(const void* batch, const float* __restrict__ b2) {
    __shared__ float sp[NG * NC];
    __shared__ float sc[NG];
    __shared__ float sb2[NC];
    int t = threadIdx.x;
    for (int j = t; j < NG * NC; j += 256) sp[j] = 0.0f;
    if (t < NG) sc[t] = 0.0f;
    if (t < NC) sb2[t] = b2[t];
    __syncthreads();
    int n = blockIdx.x * 256 + t;
    if (n < N_NODES) {
        int g = read_idx(batch, n, d_is64);
        float dis = rsqrtf(d_deg[n] + 1.0f);
        float a1 = d_a1[n];
        const unsigned* tr = H2F + (size_t)n * RW;
        const unsigned* qr = H1F + (size_t)n * RW;
#pragma unroll
        for (int q = 0; q < 5; q++) {
            float2 tv = unpack2(tr[q]);
            float2 qv = unpack2(qr[q]);
            atomicAdd(&sp[g * NC + 2*q],     dis * (tv.x + qv.x) + a1 * sb2[2*q]);
            atomicAdd(&sp[g * NC + 2*q + 1], dis * (tv.y + qv.y) + a1 * sb2[2*q+1]);
        }
        atomicAdd(&sc[g], 1.0f);
    }
    __syncthreads();
    for (int j = t; j < NG * NC; j += 256)
        if (sp[j] != 0.0f) atomicAdd(&d_pool[j], sp[j]);
    if (t < NG && sc[t] != 0.0f) atomicAdd(&d_gcnt[t], sc[t]);
}

// divide by counts, log_softmax
__global__ void __launch_bounds__(64) k_final(float* __restrict__ out) {
    int g = threadIdx.x;
    float inv = 1.0f / fmaxf(d_gcnt[g], 1.0f);
    float p[NC];
#pragma unroll
    for (int c = 0; c < NC; c++) p[c] = d_pool[g * NC + c] * inv;
    float mx = p[0];
#pragma unroll
    for (int c = 1; c < NC; c++) mx = fmaxf(mx, p[c]);
    float se = 0.0f;
#pragma unroll
    for (int c = 0; c < NC; c++) se += expf(p[c] - mx);
    float l = logf(se);
#pragma unroll
    for (int c = 0; c < NC; c++) out[g * NC + c] = p[c] - mx - l;
}

// ---------------- launch ----------------
extern "C" void kernel_launch(void* const* d_in, const int* in_sizes, int n_in,
                              void* d_out, int out_size) {
    const float* x = (const float*)d_in[0];
    const void*  ei = d_in[1];
    const void*  batch = d_in[2];
    int w = (in_sizes[3] == 1) ? 4 : 3;
    const float* W1 = (const float*)d_in[w + 0];
    const float* b1 = (const float*)d_in[w + 1];
    const float* W2 = (const float*)d_in[w + 2];
    const float* b2 = (const float*)d_in[w + 3];
    float* out = (float*)d_out;

    void* p;
    cudaGetSymbolAddress(&p, d_deg);  cudaMemsetAsync(p, 0, sizeof(float) * N_NODES);
    cudaGetSymbolAddress(&p, d_pool); cudaMemsetAsync(p, 0, sizeof(float) * NG * NC);
    cudaGetSymbolAddress(&p, d_gcnt); cudaMemsetAsync(p, 0, sizeof(float) * NG);

    k_init<<<2, 128>>>(ei, W1, W2, b1);
    k_fat <<<PACK_BLOCKS + U_BLOCKS + ZB_BLOCKS, 256>>>(ei, x);
    k_scale<<<U_BLOCKS, 256>>>();

    k_pass1<<<PACK_BLOCKS, 256>>>();
    k_post1<<<U_BLOCKS, 256>>>();
    k_pass2<<<PACK_BLOCKS, 256>>>();

    k_pool<<<U_BLOCKS, 256>>>(batch, b2);
    k_final<<<1, NG>>>(out);
}

// round 14
// speedup vs baseline: 1.3145x; 1.0318x over previous
#include <cuda_runtime.h>
#include <cuda_fp16.h>
#include <cstdint>

#define N_NODES 100000
#define N_EDGES 1600000
#define NF 128
#define NC 10
#define NG 64
#define RW 8   // half2 lanes per row: 5 class lanes + aux lane + 2 pad = 32B sector

#define PACK_BLOCKS ((N_EDGES + 255) / 256)   // 6250
#define U_BLOCKS    ((N_NODES + 255) / 256)   // 391
#define HF_UINTS    (2 * N_NODES * RW)        // 1.6M
#define ZB_BLOCKS   ((HF_UINTS / 8 + 255) / 256)  // 782 (8 uints = 32B/thread)
#define DEGZ_BLOCKS ((N_NODES / 4 + 255) / 256)   // 98 (256 float4 per block)

// ---------------- scratch ----------------
__device__ __align__(32) float    d_deg[N_NODES];        // edge-only degree
__device__ __align__(16) int2     d_rc[N_EDGES];
__device__ __align__(16) float    d_u [N_NODES * 12];    // x @ Wc (f32, 12-wide)
__device__ __align__(32) unsigned d_uf[N_NODES * RW];    // dis*u fp16x2; lane5=(dis,0)
__device__ __align__(32) unsigned d_hf[HF_UINTS];        // [h1f | h2f]
__device__ __align__(16) float    d_a1[N_NODES];
__device__ __align__(16) float    d_Wc[NF * 12];
__device__ __align__(16) float    d_bw[12];
__device__ float    d_pool[NG * NC];
__device__ float    d_gcnt[NG];
__device__ unsigned d_done;
__device__ int      d_is64;

#define H1F d_hf
#define H2F (d_hf + N_NODES * RW)

// ---------------- helpers ----------------
__device__ __forceinline__ int read_idx(const void* p, long long i, int is64) {
    return is64 ? (int)((const long long*)p)[i] : ((const int*)p)[i];
}
__device__ __forceinline__ void redv4h(unsigned* addr, uint4 v) {
    asm volatile("red.global.add.noftz.v4.f16x2 [%0], {%1,%2,%3,%4};"
                 :: "l"(addr), "r"(v.x), "r"(v.y), "r"(v.z), "r"(v.w) : "memory");
}
__device__ __forceinline__ void redv2h(unsigned* addr, unsigned a, unsigned b) {
    asm volatile("red.global.add.noftz.v2.f16x2 [%0], {%1,%2};"
                 :: "l"(addr), "r"(a), "r"(b) : "memory");
}
__device__ __forceinline__ void redh(unsigned* addr, unsigned a) {
    asm volatile("red.global.add.noftz.f16x2 [%0], %1;"
                 :: "l"(addr), "r"(a) : "memory");
}
__device__ __forceinline__ unsigned pack2(float lo, float hi) {
    __half2 h = __floats2half2_rn(lo, hi);
    return *reinterpret_cast<unsigned*>(&h);
}
__device__ __forceinline__ float2 unpack2(unsigned u) {
    __half2 h = *reinterpret_cast<__half2*>(&u);
    return make_float2(__low2float(h), __high2float(h));
}

// block 0: detect int64 + zero pool/gcnt/done ; block 1: Wc & bw ;
// blocks [2, 2+DEGZ): zero d_deg (contiguous: 256 float4 per block)
__global__ void __launch_bounds__(128) k_init(const void* ei,
                                              const float* __restrict__ W1,
                                              const float* __restrict__ W2,
                                              const float* __restrict__ b1) {
    if (blockIdx.x == 0) {
        int t = threadIdx.x;
        if (t < 32) {
            const int* p = (const int*)ei;
            unsigned ok = __ballot_sync(0xFFFFFFFFu, p[2 * t + 1] == 0);
            if (t == 0) { d_is64 = (ok == 0xFFFFFFFFu) ? 1 : 0; d_done = 0u; }
        }
        for (int j = t; j < NG * NC; j += 128) d_pool[j] = 0.0f;
        if (t < NG) d_gcnt[t] = 0.0f;
        return;
    }
    if (blockIdx.x >= 2) {
        // 128 threads, 2 consecutive float4 each -> block covers 256 contiguous float4
        int i0 = (blockIdx.x - 2) * 128 + threadIdx.x;
        float4* dz = (float4*)d_deg;
        if (i0 * 2 < N_NODES / 4)     dz[i0 * 2]     = make_float4(0,0,0,0);
        if (i0 * 2 + 1 < N_NODES / 4) dz[i0 * 2 + 1] = make_float4(0,0,0,0);
        return;
    }
    __shared__ float sW2[NF * NC];
    int t = threadIdx.x;                       // t = input-feature row
    for (int j = t; j < NF * NC; j += NF) sW2[j] = W2[j];
    __syncthreads();
    float acc[NC];
#pragma unroll
    for (int c = 0; c < NC; c++) acc[c] = 0.0f;
    for (int f = 0; f < NF; f++) {
        float w = W1[t * NF + f];
#pragma unroll
        for (int c = 0; c < NC; c++) acc[c] += w * sW2[f * NC + c];
    }
#pragma unroll
    for (int c = 0; c < NC; c++) d_Wc[t * 12 + c] = acc[c];
    d_Wc[t * 12 + 10] = 0.0f; d_Wc[t * 12 + 11] = 0.0f;
    if (t < NC) {
        float a = 0.0f;
        for (int f = 0; f < NF; f++) a += b1[f] * sW2[f * NC + t];
        d_bw[t] = a;
    }
    if (t == 0) { d_bw[10] = 0.0f; d_bw[11] = 0.0f; }
}

// Fat: blocks [0,PACK): pack rc + degree atomics;
//      blocks [PACK, PACK+U): u = x @ Wc (f32);
//      blocks [PACK+U, PACK+U+ZB): zero d_hf
__global__ void __launch_bounds__(256) k_fat(const void* ei, const float* __restrict__ x) {
    if (blockIdx.x < PACK_BLOCKS) {
        int e = blockIdx.x * 256 + threadIdx.x;
        if (e >= N_EDGES) return;
        int is64 = d_is64;
        int r = read_idx(ei, e, is64);
        int c = read_idx(ei, (long long)N_EDGES + e, is64);
        d_rc[e] = make_int2(r, c);
        atomicAdd(&d_deg[c], 1.0f);
    } else if (blockIdx.x < PACK_BLOCKS + U_BLOCKS) {
        __shared__ float4 sWc[NF * 3];
        int t = threadIdx.x;
        for (int j = t; j < NF * 3; j += 256) sWc[j] = ((const float4*)d_Wc)[j];
        __syncthreads();
        int n = (blockIdx.x - PACK_BLOCKS) * 256 + t;
        if (n >= N_NODES) return;
        float4 a0 = make_float4(0,0,0,0), a1 = a0, a2 = a0;
        const float4* xr = (const float4*)(x + (size_t)n * NF);
#pragma unroll 4
        for (int k4 = 0; k4 < NF / 4; k4++) {
            float4 xv = __ldg(&xr[k4]);
#pragma unroll
            for (int kk = 0; kk < 4; kk++) {
                float s = (kk == 0) ? xv.x : (kk == 1) ? xv.y : (kk == 2) ? xv.z : xv.w;
                int k = k4 * 4 + kk;
                float4 w0 = sWc[k * 3 + 0], w1 = sWc[k * 3 + 1], w2 = sWc[k * 3 + 2];
                a0.x += s * w0.x; a0.y += s * w0.y; a0.z += s * w0.z; a0.w += s * w0.w;
                a1.x += s * w1.x; a1.y += s * w1.y; a1.z += s * w1.z; a1.w += s * w1.w;
                a2.x += s * w2.x; a2.y += s * w2.y; a2.z += s * w2.z; a2.w += s * w2.w;
            }
        }
        float4* ur = (float4*)(d_u + (size_t)n * 12);
        ur[0] = a0; ur[1] = a1; ur[2] = a2;
    } else {
        int t = (blockIdx.x - PACK_BLOCKS - U_BLOCKS) * 256 + threadIdx.x;
        if (t * 8 < HF_UINTS) {
            uint4* p = (uint4*)d_hf + t * 2;
            p[0] = make_uint4(0u, 0u, 0u, 0u);
            p[1] = make_uint4(0u, 0u, 0u, 0u);
        }
    }
}

// u'f16 = dis * u ; lane5 = (dis, 0); lanes 6,7 = 0
__global__ void __launch_bounds__(256) k_scale() {
    int n = blockIdx.x * blockDim.x + threadIdx.x;
    if (n >= N_NODES) return;
    float dis = rsqrtf(d_deg[n] + 1.0f);
    const float4* ur = (const float4*)(d_u + (size_t)n * 12);
    float4 u0 = ur[0], u1 = ur[1], u2 = ur[2];
    uint4* o = (uint4*)(d_uf + (size_t)n * RW);
    o[0] = make_uint4(pack2(u0.x * dis, u0.y * dis),
                      pack2(u0.z * dis, u0.w * dis),
                      pack2(u1.x * dis, u1.y * dis),
                      pack2(u1.z * dis, u1.w * dis));
    o[1] = make_uint4(pack2(u2.x * dis, u2.y * dis),
                      pack2(dis, 0.0f), 0u, 0u);
}

// pass1: scatter-copy u' rows into h1f: one v4 RED + one v2 RED (lanes 0-5)
__global__ void __launch_bounds__(256) k_pass1() {
    int e = blockIdx.x * blockDim.x + threadIdx.x;
    if (e >= N_EDGES) return;
    int2 rc = __ldg(&d_rc[e]);
    const uint4* s = (const uint4*)(d_uf + (size_t)rc.x * RW);
    uint4 p0 = __ldg(&s[0]);
    uint2 p1 = __ldg((const uint2*)(s + 1));  // .x=lane4, .y=lane5(dis)
    unsigned* d = H1F + (size_t)rc.y * RW;
    redv4h(d, p0);
    redv2h(d + 4, p1.x, p1.y);
}

// post1: h1_full = dis*(S + u') + a1*bw ; write h1' = dis*h1_full (fp16), lane5=0
__global__ void __launch_bounds__(256) k_post1() {
    __shared__ float sbw[NC];
    if (threadIdx.x < NC) sbw[threadIdx.x] = d_bw[threadIdx.x];
    __syncthreads();
    int n = blockIdx.x * blockDim.x + threadIdx.x;
    if (n >= N_NODES) return;
    float dis = rsqrtf(d_deg[n] + 1.0f);
    uint4* hr = (uint4*)(H1F + (size_t)n * RW);
    const uint4* ur = (const uint4*)(d_uf + (size_t)n * RW);
    uint4 h0 = hr[0], h1 = hr[1];
    uint4 u0 = ur[0], u1 = ur[1];
    float S[NC], U[NC];
    {
        float2 a, b;
        a = unpack2(h0.x); S[0]=a.x; S[1]=a.y;  a = unpack2(h0.y); S[2]=a.x; S[3]=a.y;
        a = unpack2(h0.z); S[4]=a.x; S[5]=a.y;  a = unpack2(h0.w); S[6]=a.x; S[7]=a.y;
        a = unpack2(h1.x); S[8]=a.x; S[9]=a.y;
        b = unpack2(u0.x); U[0]=b.x; U[1]=b.y;  b = unpack2(u0.y); U[2]=b.x; U[3]=b.y;
        b = unpack2(u0.z); U[4]=b.x; U[5]=b.y;  b = unpack2(u0.w); U[6]=b.x; U[7]=b.y;
        b = unpack2(u1.x); U[8]=b.x; U[9]=b.y;
    }
    float sumdis = unpack2(h1.y).x;
    float a1 = dis * (sumdis + dis);
    d_a1[n] = a1;
#pragma unroll
    for (int c = 0; c < NC; c++) {
        float h = dis * (S[c] + U[c]) + a1 * sbw[c];
        S[c] = dis * h;                       // prescale for pass2
    }
    hr[0] = make_uint4(pack2(S[0],S[1]), pack2(S[2],S[3]), pack2(S[4],S[5]), pack2(S[6],S[7]));
    hr[1] = make_uint4(pack2(S[8],S[9]), 0u, 0u, 0u);
}

// pass2: scatter-copy h1' rows into h2f: one v4 RED + one scalar RED (lanes 0-4)
__global__ void __launch_bounds__(256) k_pass2() {
    int e = blockIdx.x * blockDim.x + threadIdx.x;
    if (e >= N_EDGES) return;
    int2 rc = __ldg(&d_rc[e]);
    const uint4* s = (const uint4*)(H1F + (size_t)rc.x * RW);
    uint4 p0 = __ldg(&s[0]);
    unsigned p4 = __ldg((const unsigned*)(s + 1));   // lane4
    unsigned* d = H2F + (size_t)rc.y * RW;
    redv4h(d, p0);
    redh(d + 4, p4);
}

// pool + fused final: per-graph mean-pool accumulate; last block does log_softmax
__global__ void __launch_bounds__(256) k_pool(const void* batch, const float* __restrict__ b2,
                                              float* __restrict__ out) {
    __shared__ float sp[NG * NC];
    __shared__ float sc[NG];
    __shared__ float sb2[NC];
    __shared__ unsigned slast;
    int t = threadIdx.x;
    for (int j = t; j < NG * NC; j += 256) sp[j] = 0.0f;
    if (t < NG) sc[t] = 0.0f;
    if (t < NC) sb2[t] = b2[t];
    __syncthreads();
    int n = blockIdx.x * 256 + t;
    if (n < N_NODES) {
        int g = read_idx(batch, n, d_is64);
        float dis = rsqrtf(d_deg[n] + 1.0f);
        float a1 = d_a1[n];
        const unsigned* tr = H2F + (size_t)n * RW;
        const unsigned* qr = H1F + (size_t)n * RW;
#pragma unroll
        for (int q = 0; q < 5; q++) {
            float2 tv = unpack2(tr[q]);
            float2 qv = unpack2(qr[q]);
            atomicAdd(&sp[g * NC + 2*q],     dis * (tv.x + qv.x) + a1 * sb2[2*q]);
            atomicAdd(&sp[g * NC + 2*q + 1], dis * (tv.y + qv.y) + a1 * sb2[2*q+1]);
        }
        atomicAdd(&sc[g], 1.0f);
    }
    __syncthreads();
    for (int j = t; j < NG * NC; j += 256)
        if (sp[j] != 0.0f) atomicAdd(&d_pool[j], sp[j]);
    if (t < NG && sc[t] != 0.0f) atomicAdd(&d_gcnt[t], sc[t]);

    // completion counter: last block computes log_softmax
    __threadfence();
    if (t == 0) slast = atomicAdd(&d_done, 1u);
    __syncthreads();
    if (slast == (unsigned)(gridDim.x - 1)) {
        __threadfence();   // acquire: make all blocks' d_pool/d_gcnt visible
        if (t < NG) {
            int g = t;
            float inv = 1.0f / fmaxf(d_gcnt[g], 1.0f);
            float p[NC];
#pragma unroll
            for (int c = 0; c < NC; c++) p[c] = d_pool[g * NC + c] * inv;
            float mx = p[0];
#pragma unroll
            for (int c = 1; c < NC; c++) mx = fmaxf(mx, p[c]);
            float se = 0.0f;
#pragma unroll
            for (int c = 0; c < NC; c++) se += expf(p[c] - mx);
            float l = logf(se);
#pragma unroll
            for (int c = 0; c < NC; c++) out[g * NC + c] = p[c] - mx - l;
        }
    }
}

// ---------------- launch ----------------
extern "C" void kernel_launch(void* const* d_in, const int* in_sizes, int n_in,
                              void* d_out, int out_size) {
    const float* x = (const float*)d_in[0];
    const void*  ei = d_in[1];
    const void*  batch = d_in[2];
    int w = (in_sizes[3] == 1) ? 4 : 3;
    const float* W1 = (const float*)d_in[w + 0];
    const float* b1 = (const float*)d_in[w + 1];
    const float* W2 = (const float*)d_in[w + 2];
    const float* b2 = (const float*)d_in[w + 3];
    float* out = (float*)d_out;

    k_init<<<2 + DEGZ_BLOCKS, 128>>>(ei, W1, W2, b1);
    k_fat <<<PACK_BLOCKS + U_BLOCKS + ZB_BLOCKS, 256>>>(ei, x);
    k_scale<<<U_BLOCKS, 256>>>();

    k_pass1<<<PACK_BLOCKS, 256>>>();
    k_post1<<<U_BLOCKS, 256>>>();
    k_pass2<<<PACK_BLOCKS, 256>>>();

    k_pool<<<U_BLOCKS, 256>>>(batch, b2, out);
}

// round 15
// speedup vs baseline: 1.3443x; 1.0226x over previous
#include <cuda_runtime.h>
#include <cuda_fp16.h>
#include <cstdint>

#define N_NODES 100000
#define N_EDGES 1600000
#define NF 128
#define NC 10
#define NG 64
#define RW 8   // half2 lanes per row: 5 class lanes + aux lane + 2 pad = 32B sector

#define E2_BLOCKS  ((N_EDGES / 2 + 255) / 256)    // 3125 (2 edges/thread)
#define U_BLOCKS   ((N_NODES + 255) / 256)        // 391
#define HF_UINTS   (2 * N_NODES * RW)             // 1.6M
#define ZB_BLOCKS  ((HF_UINTS / 8 + 255) / 256)   // 782 (8 uints = 32B/thread)
#define DEGZ_BLOCKS ((N_NODES / 4 + 127) / 128)   // 196 (128 thr * 2 float4 per block)

// ---------------- scratch ----------------
__device__ __align__(32) float    d_deg[N_NODES];        // edge-only degree
__device__ __align__(16) float    d_u [N_NODES * 12];    // x @ Wc (f32, 12-wide)
__device__ __align__(32) unsigned d_uf[N_NODES * RW];    // dis*u fp16x2; lane5=(dis,0)
__device__ __align__(32) unsigned d_hf[HF_UINTS];        // [h1f | h2f]
__device__ __align__(16) float    d_a1[N_NODES];
__device__ __align__(16) float    d_Wc[NF * 12];
__device__ __align__(16) float    d_bw[12];
__device__ float    d_pool[NG * NC];
__device__ float    d_gcnt[NG];
__device__ unsigned d_done;
__device__ int      d_is64;

#define H1F d_hf
#define H2F (d_hf + N_NODES * RW)

// ---------------- helpers ----------------
__device__ __forceinline__ int read_idx(const void* p, long long i, int is64) {
    return is64 ? (int)((const long long*)p)[i] : ((const int*)p)[i];
}
__device__ __forceinline__ void redv4h(unsigned* addr, uint4 v) {
    asm volatile("red.global.add.noftz.v4.f16x2 [%0], {%1,%2,%3,%4};"
                 :: "l"(addr), "r"(v.x), "r"(v.y), "r"(v.z), "r"(v.w) : "memory");
}
__device__ __forceinline__ void redv2h(unsigned* addr, unsigned a, unsigned b) {
    asm volatile("red.global.add.noftz.v2.f16x2 [%0], {%1,%2};"
                 :: "l"(addr), "r"(a), "r"(b) : "memory");
}
__device__ __forceinline__ void redh(unsigned* addr, unsigned a) {
    asm volatile("red.global.add.noftz.f16x2 [%0], %1;"
                 :: "l"(addr), "r"(a) : "memory");
}
__device__ __forceinline__ unsigned pack2(float lo, float hi) {
    __half2 h = __floats2half2_rn(lo, hi);
    return *reinterpret_cast<unsigned*>(&h);
}
__device__ __forceinline__ float2 unpack2(unsigned u) {
    __half2 h = *reinterpret_cast<__half2*>(&u);
    return make_float2(__low2float(h), __high2float(h));
}
// load 2 edges (r0,c0),(r1,c1) for thread t from the two ei streams
__device__ __forceinline__ void load_edge2(const void* ei, int t, int is64,
                                           int& r0, int& c0, int& r1, int& c1) {
    if (is64) {
        longlong2 vr = __ldg((const longlong2*)ei + t);
        longlong2 vc = __ldg((const longlong2*)ei + (N_EDGES / 2) + t);
        r0 = (int)vr.x; r1 = (int)vr.y; c0 = (int)vc.x; c1 = (int)vc.y;
    } else {
        int2 vr = __ldg((const int2*)ei + t);
        int2 vc = __ldg((const int2*)ei + (N_EDGES / 2) + t);
        r0 = vr.x; r1 = vr.y; c0 = vc.x; c1 = vc.y;
    }
}

// block 0: detect int64 + zero pool/gcnt/done ; block 1: Wc & bw ;
// blocks [2, 2+DEGZ): zero d_deg (contiguous)
__global__ void __launch_bounds__(128) k_init(const void* ei,
                                              const float* __restrict__ W1,
                                              const float* __restrict__ W2,
                                              const float* __restrict__ b1) {
    if (blockIdx.x == 0) {
        int t = threadIdx.x;
        if (t < 32) {
            const int* p = (const int*)ei;
            unsigned ok = __ballot_sync(0xFFFFFFFFu, p[2 * t + 1] == 0);
            if (t == 0) { d_is64 = (ok == 0xFFFFFFFFu) ? 1 : 0; d_done = 0u; }
        }
        for (int j = t; j < NG * NC; j += 128) d_pool[j] = 0.0f;
        if (t < NG) d_gcnt[t] = 0.0f;
        return;
    }
    if (blockIdx.x >= 2) {
        int i0 = (blockIdx.x - 2) * 128 + threadIdx.x;
        float4* dz = (float4*)d_deg;
        if (i0 * 2 < N_NODES / 4)     dz[i0 * 2]     = make_float4(0,0,0,0);
        if (i0 * 2 + 1 < N_NODES / 4) dz[i0 * 2 + 1] = make_float4(0,0,0,0);
        return;
    }
    __shared__ float sW2[NF * NC];
    int t = threadIdx.x;                       // t = input-feature row
    for (int j = t; j < NF * NC; j += NF) sW2[j] = W2[j];
    __syncthreads();
    float acc[NC];
#pragma unroll
    for (int c = 0; c < NC; c++) acc[c] = 0.0f;
    for (int f = 0; f < NF; f++) {
        float w = W1[t * NF + f];
#pragma unroll
        for (int c = 0; c < NC; c++) acc[c] += w * sW2[f * NC + c];
    }
#pragma unroll
    for (int c = 0; c < NC; c++) d_Wc[t * 12 + c] = acc[c];
    d_Wc[t * 12 + 10] = 0.0f; d_Wc[t * 12 + 11] = 0.0f;
    if (t < NC) {
        float a = 0.0f;
        for (int f = 0; f < NF; f++) a += b1[f] * sW2[f * NC + t];
        d_bw[t] = a;
    }
    if (t == 0) { d_bw[10] = 0.0f; d_bw[11] = 0.0f; }
}

// Fat: blocks [0,E2): deg atomics (2 edges/thread, col stream only);
//      blocks [E2, E2+U): u = x @ Wc (f32);
//      blocks [E2+U, E2+U+ZB): zero d_hf
__global__ void __launch_bounds__(256) k_fat(const void* ei, const float* __restrict__ x) {
    if (blockIdx.x < E2_BLOCKS) {
        int t = blockIdx.x * 256 + threadIdx.x;
        if (t * 2 >= N_EDGES) return;
        int c0, c1;
        if (d_is64) {
            longlong2 v = __ldg((const longlong2*)ei + (N_EDGES / 2) + t);
            c0 = (int)v.x; c1 = (int)v.y;
        } else {
            int2 v = __ldg((const int2*)ei + (N_EDGES / 2) + t);
            c0 = v.x; c1 = v.y;
        }
        atomicAdd(&d_deg[c0], 1.0f);
        atomicAdd(&d_deg[c1], 1.0f);
    } else if (blockIdx.x < E2_BLOCKS + U_BLOCKS) {
        __shared__ float4 sWc[NF * 3];
        int t = threadIdx.x;
        for (int j = t; j < NF * 3; j += 256) sWc[j] = ((const float4*)d_Wc)[j];
        __syncthreads();
        int n = (blockIdx.x - E2_BLOCKS) * 256 + t;
        if (n >= N_NODES) return;
        float4 a0 = make_float4(0,0,0,0), a1 = a0, a2 = a0;
        const float4* xr = (const float4*)(x + (size_t)n * NF);
#pragma unroll 4
        for (int k4 = 0; k4 < NF / 4; k4++) {
            float4 xv = __ldg(&xr[k4]);
#pragma unroll
            for (int kk = 0; kk < 4; kk++) {
                float s = (kk == 0) ? xv.x : (kk == 1) ? xv.y : (kk == 2) ? xv.z : xv.w;
                int k = k4 * 4 + kk;
                float4 w0 = sWc[k * 3 + 0], w1 = sWc[k * 3 + 1], w2 = sWc[k * 3 + 2];
                a0.x += s * w0.x; a0.y += s * w0.y; a0.z += s * w0.z; a0.w += s * w0.w;
                a1.x += s * w1.x; a1.y += s * w1.y; a1.z += s * w1.z; a1.w += s * w1.w;
                a2.x += s * w2.x; a2.y += s * w2.y; a2.z += s * w2.z; a2.w += s * w2.w;
            }
        }
        float4* ur = (float4*)(d_u + (size_t)n * 12);
        ur[0] = a0; ur[1] = a1; ur[2] = a2;
    } else {
        int t = (blockIdx.x - E2_BLOCKS - U_BLOCKS) * 256 + threadIdx.x;
        if (t * 8 < HF_UINTS) {
            uint4* p = (uint4*)d_hf + t * 2;
            p[0] = make_uint4(0u, 0u, 0u, 0u);
            p[1] = make_uint4(0u, 0u, 0u, 0u);
        }
    }
}

// u'f16 = dis * u ; lane5 = (dis, 0); lanes 6,7 = 0
__global__ void __launch_bounds__(256) k_scale() {
    int n = blockIdx.x * blockDim.x + threadIdx.x;
    if (n >= N_NODES) return;
    float dis = rsqrtf(d_deg[n] + 1.0f);
    const float4* ur = (const float4*)(d_u + (size_t)n * 12);
    float4 u0 = ur[0], u1 = ur[1], u2 = ur[2];
    uint4* o = (uint4*)(d_uf + (size_t)n * RW);
    o[0] = make_uint4(pack2(u0.x * dis, u0.y * dis),
                      pack2(u0.z * dis, u0.w * dis),
                      pack2(u1.x * dis, u1.y * dis),
                      pack2(u1.z * dis, u1.w * dis));
    o[1] = make_uint4(pack2(u2.x * dis, u2.y * dis),
                      pack2(dis, 0.0f), 0u, 0u);
}

// pass1: 2 edges/thread, indices straight from ei; v4+v2 REDs per edge
__global__ void __launch_bounds__(256) k_pass1(const void* ei) {
    int t = blockIdx.x * 256 + threadIdx.x;
    if (t * 2 >= N_EDGES) return;
    int r0, c0, r1, c1;
    load_edge2(ei, t, d_is64, r0, c0, r1, c1);
    const uint4* sA = (const uint4*)(d_uf + (size_t)r0 * RW);
    const uint4* sB = (const uint4*)(d_uf + (size_t)r1 * RW);
    uint4 pa = __ldg(&sA[0]); uint2 qa = __ldg((const uint2*)(sA + 1));
    uint4 pb = __ldg(&sB[0]); uint2 qb = __ldg((const uint2*)(sB + 1));
    unsigned* dA = H1F + (size_t)c0 * RW;
    unsigned* dB = H1F + (size_t)c1 * RW;
    redv4h(dA, pa); redv2h(dA + 4, qa.x, qa.y);
    redv4h(dB, pb); redv2h(dB + 4, qb.x, qb.y);
}

// post1: h1_full = dis*(S + u') + a1*bw ; write h1' = dis*h1_full (fp16), lane5=0
__global__ void __launch_bounds__(256) k_post1() {
    __shared__ float sbw[NC];
    if (threadIdx.x < NC) sbw[threadIdx.x] = d_bw[threadIdx.x];
    __syncthreads();
    int n = blockIdx.x * blockDim.x + threadIdx.x;
    if (n >= N_NODES) return;
    float dis = rsqrtf(d_deg[n] + 1.0f);
    uint4* hr = (uint4*)(H1F + (size_t)n * RW);
    const uint4* ur = (const uint4*)(d_uf + (size_t)n * RW);
    uint4 h0 = hr[0], h1 = hr[1];
    uint4 u0 = ur[0], u1 = ur[1];
    float S[NC], U[NC];
    {
        float2 a, b;
        a = unpack2(h0.x); S[0]=a.x; S[1]=a.y;  a = unpack2(h0.y); S[2]=a.x; S[3]=a.y;
        a = unpack2(h0.z); S[4]=a.x; S[5]=a.y;  a = unpack2(h0.w); S[6]=a.x; S[7]=a.y;
        a = unpack2(h1.x); S[8]=a.x; S[9]=a.y;
        b = unpack2(u0.x); U[0]=b.x; U[1]=b.y;  b = unpack2(u0.y); U[2]=b.x; U[3]=b.y;
        b = unpack2(u0.z); U[4]=b.x; U[5]=b.y;  b = unpack2(u0.w); U[6]=b.x; U[7]=b.y;
        b = unpack2(u1.x); U[8]=b.x; U[9]=b.y;
    }
    float sumdis = unpack2(h1.y).x;
    float a1 = dis * (sumdis + dis);
    d_a1[n] = a1;
#pragma unroll
    for (int c = 0; c < NC; c++) {
        float h = dis * (S[c] + U[c]) + a1 * sbw[c];
        S[c] = dis * h;                       // prescale for pass2
    }
    hr[0] = make_uint4(pack2(S[0],S[1]), pack2(S[2],S[3]), pack2(S[4],S[5]), pack2(S[6],S[7]));
    hr[1] = make_uint4(pack2(S[8],S[9]), 0u, 0u, 0u);
}

// pass2: 2 edges/thread, indices straight from ei; v4+scalar REDs per edge
__global__ void __launch_bounds__(256) k_pass2(const void* ei) {
    int t = blockIdx.x * 256 + threadIdx.x;
    if (t * 2 >= N_EDGES) return;
    int r0, c0, r1, c1;
    load_edge2(ei, t, d_is64, r0, c0, r1, c1);
    const uint4* sA = (const uint4*)(H1F + (size_t)r0 * RW);
    const uint4* sB = (const uint4*)(H1F + (size_t)r1 * RW);
    uint4 pa = __ldg(&sA[0]); unsigned qa = __ldg((const unsigned*)(sA + 1));
    uint4 pb = __ldg(&sB[0]); unsigned qb = __ldg((const unsigned*)(sB + 1));
    unsigned* dA = H2F + (size_t)c0 * RW;
    unsigned* dB = H2F + (size_t)c1 * RW;
    redv4h(dA, pa); redh(dA + 4, qa);
    redv4h(dB, pb); redh(dB + 4, qb);
}

// pool + fused final: per-graph mean-pool accumulate; last block does log_softmax
__global__ void __launch_bounds__(256) k_pool(const void* batch, const float* __restrict__ b2,
                                              float* __restrict__ out) {
    __shared__ float sp[NG * NC];
    __shared__ float sc[NG];
    __shared__ float sb2[NC];
    __shared__ unsigned slast;
    int t = threadIdx.x;
    for (int j = t; j < NG * NC; j += 256) sp[j] = 0.0f;
    if (t < NG) sc[t] = 0.0f;
    if (t < NC) sb2[t] = b2[t];
    __syncthreads();
    int n = blockIdx.x * 256 + t;
    if (n < N_NODES) {
        int g = read_idx(batch, n, d_is64);
        float dis = rsqrtf(d_deg[n] + 1.0f);
        float a1 = d_a1[n];
        const unsigned* tr = H2F + (size_t)n * RW;
        const unsigned* qr = H1F + (size_t)n * RW;
#pragma unroll
        for (int q = 0; q < 5; q++) {
            float2 tv = unpack2(tr[q]);
            float2 qv = unpack2(qr[q]);
            atomicAdd(&sp[g * NC + 2*q],     dis * (tv.x + qv.x) + a1 * sb2[2*q]);
            atomicAdd(&sp[g * NC + 2*q + 1], dis * (tv.y + qv.y) + a1 * sb2[2*q+1]);
        }
        atomicAdd(&sc[g], 1.0f);
    }
    __syncthreads();
    for (int j = t; j < NG * NC; j += 256)
        if (sp[j] != 0.0f) atomicAdd(&d_pool[j], sp[j]);
    if (t < NG && sc[t] != 0.0f) atomicAdd(&d_gcnt[t], sc[t]);

    __threadfence();
    if (t == 0) slast = atomicAdd(&d_done, 1u);
    __syncthreads();
    if (slast == (unsigned)(gridDim.x - 1)) {
        __threadfence();
        if (t < NG) {
            int g = t;
            float inv = 1.0f / fmaxf(d_gcnt[g], 1.0f);
            float p[NC];
#pragma unroll
            for (int c = 0; c < NC; c++) p[c] = d_pool[g * NC + c] * inv;
            float mx = p[0];
#pragma unroll
            for (int c = 1; c < NC; c++) mx = fmaxf(mx, p[c]);
            float se = 0.0f;
#pragma unroll
            for (int c = 0; c < NC; c++) se += expf(p[c] - mx);
            float l = logf(se);
#pragma unroll
            for (int c = 0; c < NC; c++) out[g * NC + c] = p[c] - mx - l;
        }
    }
}

// ---------------- launch ----------------
extern "C" void kernel_launch(void* const* d_in, const int* in_sizes, int n_in,
                              void* d_out, int out_size) {
    const float* x = (const float*)d_in[0];
    const void*  ei = d_in[1];
    const void*  batch = d_in[2];
    int w = (in_sizes[3] == 1) ? 4 : 3;
    const float* W1 = (const float*)d_in[w + 0];
    const float* b1 = (const float*)d_in[w + 1];
    const float* W2 = (const float*)d_in[w + 2];
    const float* b2 = (const float*)d_in[w + 3];
    float* out = (float*)d_out;

    k_init<<<2 + DEGZ_BLOCKS, 128>>>(ei, W1, W2, b1);
    k_fat <<<E2_BLOCKS + U_BLOCKS + ZB_BLOCKS, 256>>>(ei, x);
    k_scale<<<U_BLOCKS, 256>>>();

    k_pass1<<<E2_BLOCKS, 256>>>(ei);
    k_post1<<<U_BLOCKS, 256>>>();
    k_pass2<<<E2_BLOCKS, 256>>>(ei);

    k_pool<<<U_BLOCKS, 256>>>(batch, b2, out);
}